// round 9
// baseline (speedup 1.0000x reference)
#include <cuda_runtime.h>
#include <cuda_fp16.h>
#include <cstdint>

#define NN 50000
#define NE 800000
#define D  256
#define BN_EPS 1e-5f
#define NSCB 196   // ceil(NN/256) scan blocks

// ---------------- scratch (static device allocations) ----------------
__device__ __half g_h[NN * D];       // 25.6 MB: h = x @ W^T in fp16
__device__ float g_dinv[NN];
__device__ int   g_cnt[NN];
__device__ int   g_off[NN + 1];      // local-exclusive offsets (pre-boff)
__device__ int   g_src[NE];
__device__ int   g_bsum[NSCB];
__device__ int   g_boff[NSCB];       // published by k_fill block 0
__device__ float g_bnstat[2 * D];
__device__ float g_bn_a[D];
__device__ float g_bn_b[D];

// ---------------- multi-block scan helper ----------------
__device__ __forceinline__ int block_incl_scan256(int v, int tid) {
    __shared__ int ws[8];
    int lane = tid & 31, w = tid >> 5;
    int inc = v;
#pragma unroll
    for (int o = 1; o < 32; o <<= 1) {
        int n = __shfl_up_sync(0xFFFFFFFFu, inc, o);
        if (lane >= o) inc += n;
    }
    if (lane == 31) ws[w] = inc;
    __syncthreads();
    if (w == 0) {
        int s = (lane < 8) ? ws[lane] : 0;
#pragma unroll
        for (int o = 1; o < 8; o <<= 1) {
            int n = __shfl_up_sync(0xFFFFFFFFu, s, o);
            if (lane >= o) s += n;
        }
        if (lane < 8) ws[lane] = s;
    }
    __syncthreads();
    return inc + (w > 0 ? ws[w - 1] : 0);
}

// ---------------- GEMM (+fused edge count): H(fp16) = X @ W^T ----------------
// BM=128 BN=64 BK=32, 256 threads = 8 warps (4m x 2n), warp tile 32x32.
#define GPAD 20
#define EPB 512   // edges counted per block (1564 blocks * 512 >= NE)

__device__ __forceinline__ unsigned pack_bf16x2(float k0, float k1) {
    unsigned r;
    asm("cvt.rn.bf16x2.f32 %0, %1, %2;" : "=r"(r) : "f"(k1), "f"(k0));
    return r;
}

#define MMA_BF16(acc, a, b) \
    asm volatile("mma.sync.aligned.m16n8k16.row.col.f32.bf16.bf16.f32 " \
                 "{%0,%1,%2,%3},{%4,%5,%6,%7},{%8,%9},{%0,%1,%2,%3};" \
                 : "+f"(acc[0]), "+f"(acc[1]), "+f"(acc[2]), "+f"(acc[3]) \
                 : "r"(a[0]), "r"(a[1]), "r"(a[2]), "r"(a[3]), "r"(b[0]), "r"(b[1]))

#define LDSM4(r, addr) \
    asm volatile("ldmatrix.sync.aligned.m8n8.x4.shared.b16 {%0,%1,%2,%3}, [%4];" \
                 : "=r"(r[0]), "=r"(r[1]), "=r"(r[2]), "=r"(r[3]) : "r"(addr))

// truncation split: hi = top16 bits (exact bf16), lo = rounded remainder
__device__ __forceinline__ void split2(float a, float b, unsigned& hi, unsigned& lo) {
    hi = __byte_perm(__float_as_uint(a), __float_as_uint(b), 0x7632);
    float la = a - __uint_as_float(hi << 16);
    float lb = b - __uint_as_float(hi & 0xFFFF0000u);
    lo = pack_bf16x2(la, lb);
}

__global__ __launch_bounds__(256) void k_gemm_bf16(const float* __restrict__ X,
                                                   const float* __restrict__ W,
                                                   __half* __restrict__ H,
                                                   const int* __restrict__ ei) {
    // --- fused edge-degree count: this block's slice ---
    {
        int bid = blockIdx.y * gridDim.x + blockIdx.x;
        int e0 = bid * EPB;
#pragma unroll
        for (int p = 0; p < 2; p++) {
            int e = e0 + threadIdx.x + p * 256;
            if (e < NE && e < e0 + EPB) atomicAdd(&g_cnt[ei[NE + e]], 1);
        }
    }

    __shared__ unsigned Ahi[128][GPAD], Alo[128][GPAD];
    __shared__ unsigned Bhi[64][GPAD],  Blo[64][GPAD];

    const int bm = blockIdx.x * 128;
    const int bn = blockIdx.y * 64;
    const int tid = threadIdx.x;
    const int warp = tid >> 5, lane = tid & 31;
    const int wm = warp & 3, wn = warp >> 2;
    const int grp = lane >> 2, tig = lane & 3;

    const int lr = lane & 7, sel = lane >> 3;
    const int a_row = ((sel & 1) ? 8 : 0) + lr;
    const int a_col = (sel & 2) ? 4 : 0;
    const int b_row = ((sel & 2) ? 8 : 0) + lr;
    const int b_col = (sel & 1) ? 4 : 0;

    const uint32_t sAhi = (uint32_t)__cvta_generic_to_shared(&Ahi[0][0]);
    const uint32_t sAlo = (uint32_t)__cvta_generic_to_shared(&Alo[0][0]);
    const uint32_t sBhi = (uint32_t)__cvta_generic_to_shared(&Bhi[0][0]);
    const uint32_t sBlo = (uint32_t)__cvta_generic_to_shared(&Blo[0][0]);

    float acc[2][4][4];
#pragma unroll
    for (int mi = 0; mi < 2; mi++)
#pragma unroll
        for (int ni = 0; ni < 4; ni++)
#pragma unroll
            for (int q = 0; q < 4; q++) acc[mi][ni][q] = 0.0f;

    for (int k0 = 0; k0 < D; k0 += 32) {
#pragma unroll
        for (int p = 0; p < 4; p++) {
            int f = tid + p * 256;
            int row = f >> 3;
            int q = f & 7;
            float4 v = make_float4(0.f, 0.f, 0.f, 0.f);
            int gr = bm + row;
            if (gr < NN) v = *(const float4*)&X[(size_t)gr * D + k0 + q * 4];
            unsigned h0, l0, h1, l1;
            split2(v.x, v.y, h0, l0);
            split2(v.z, v.w, h1, l1);
            Ahi[row][q * 2]     = h0;
            Ahi[row][q * 2 + 1] = h1;
            Alo[row][q * 2]     = l0;
            Alo[row][q * 2 + 1] = l1;
        }
#pragma unroll
        for (int p = 0; p < 2; p++) {
            int f = tid + p * 256;
            int row = f >> 3;
            int q = f & 7;
            float4 v = *(const float4*)&W[(size_t)(bn + row) * D + k0 + q * 4];
            unsigned h0, l0, h1, l1;
            split2(v.x, v.y, h0, l0);
            split2(v.z, v.w, h1, l1);
            Bhi[row][q * 2]     = h0;
            Bhi[row][q * 2 + 1] = h1;
            Blo[row][q * 2]     = l0;
            Blo[row][q * 2 + 1] = l1;
        }
        __syncthreads();

#pragma unroll
        for (int ks = 0; ks < 16; ks += 8) {
            unsigned ah[2][4], al[2][4], bh[2][4], bl[2][4];
#pragma unroll
            for (int mi = 0; mi < 2; mi++) {
                uint32_t off = (uint32_t)(((wm * 32 + mi * 16 + a_row) * GPAD + ks + a_col) << 2);
                LDSM4(ah[mi], sAhi + off);
                LDSM4(al[mi], sAlo + off);
            }
#pragma unroll
            for (int p = 0; p < 2; p++) {
                uint32_t off = (uint32_t)(((wn * 32 + p * 16 + b_row) * GPAD + ks + b_col) << 2);
                LDSM4(bh[p], sBhi + off);
                LDSM4(bl[p], sBlo + off);
            }
#pragma unroll
            for (int mi = 0; mi < 2; mi++)
#pragma unroll
                for (int ni = 0; ni < 4; ni++) {
                    int p = ni >> 1, o = (ni & 1) * 2;
                    MMA_BF16(acc[mi][ni], ah[mi], (&bh[p][o]));
                    MMA_BF16(acc[mi][ni], ah[mi], (&bl[p][o]));
                    MMA_BF16(acc[mi][ni], al[mi], (&bh[p][o]));
                }
        }
        __syncthreads();
    }

#pragma unroll
    for (int mi = 0; mi < 2; mi++)
#pragma unroll
        for (int ni = 0; ni < 4; ni++) {
            int r0 = bm + wm * 32 + mi * 16 + grp;
            int c0 = bn + wn * 32 + ni * 8 + tig * 2;
            if (r0 < NN)
                *(__half2*)&H[(size_t)r0 * D + c0] = __floats2half2_rn(acc[mi][ni][0], acc[mi][ni][1]);
            if (r0 + 8 < NN)
                *(__half2*)&H[(size_t)(r0 + 8) * D + c0] = __floats2half2_rn(acc[mi][ni][2], acc[mi][ni][3]);
        }
}

// ---------------- scan phase 1 + dinv ----------------
__global__ __launch_bounds__(256) void k_scan1(void) {
    int tid = threadIdx.x;
    int idx = blockIdx.x * 256 + tid;
    int v = (idx < NN) ? g_cnt[idx] : 0;
    if (idx < NN) g_dinv[idx] = rsqrtf((float)(v + 1));
    int inc = block_incl_scan256(v, tid);
    if (idx < NN) g_off[idx] = inc - v;
    if (tid == 255) g_bsum[blockIdx.x] = inc;
}

// ---------------- fill CSR (inline block-sum scan; publishes g_boff) ----------------
__global__ __launch_bounds__(256) void k_fill(const int* __restrict__ ei) {
    __shared__ int sboff[NSCB];
    int t = threadIdx.x;
    {
        int v = (t < NSCB) ? g_bsum[t] : 0;
        int inc = block_incl_scan256(v, t);
        if (t < NSCB) {
            sboff[t] = inc - v;
            if (blockIdx.x == 0) g_boff[t] = inc - v;   // for k_gather_bn
        }
    }
    __syncthreads();
    int e = blockIdx.x * 256 + t;
    if (e < NE) {
        int r = ei[e];
        int c = ei[NE + e];
        int pos = g_off[c] + sboff[c >> 8] + atomicSub(&g_cnt[c], 1) - 1;
        g_src[pos] = r;
    }
}

// ---------------- fused gather + bias + BN-stats ----------------
// 64 threads: thread d handles columns 4d..4d+3 (one uint2 = 4 fp16); grid-stride.
__global__ __launch_bounds__(64) void k_gather_bn(const float* __restrict__ bias,
                                                  float* __restrict__ out) {
    const int d = threadIdx.x;
    const uint2* __restrict__ H4 = (const uint2*)g_h;   // 64 uint2 per row
    const float4 bi = *(const float4*)&bias[4 * d];
    float s0 = 0.f, s1 = 0.f, s2 = 0.f, s3 = 0.f;
    float q0 = 0.f, q1 = 0.f, q2 = 0.f, q3 = 0.f;

    for (int c = blockIdx.x; c < NN; c += gridDim.x) {
        const float dc = g_dinv[c];
        const int beg = g_off[c] + g_boff[c >> 8];
        const int end = (c + 1 < NN) ? g_off[c + 1] + g_boff[(c + 1) >> 8] : NE;

        uint2 u = H4[(size_t)c * 64 + d];
        float2 ha = __half22float2(*(__half2*)&u.x);
        float2 hb = __half22float2(*(__half2*)&u.y);
        float a0 = ha.x * dc, a1 = ha.y * dc, a2 = hb.x * dc, a3 = hb.y * dc;

        int j = beg;
        for (; j + 3 < end; j += 4) {
            int r0 = __ldg(&g_src[j]);
            int r1 = __ldg(&g_src[j + 1]);
            int r2 = __ldg(&g_src[j + 2]);
            int r3 = __ldg(&g_src[j + 3]);
            float w0 = g_dinv[r0], w1 = g_dinv[r1], w2 = g_dinv[r2], w3 = g_dinv[r3];
            uint2 u0 = H4[(size_t)r0 * 64 + d];
            uint2 u1 = H4[(size_t)r1 * 64 + d];
            uint2 u2 = H4[(size_t)r2 * 64 + d];
            uint2 u3 = H4[(size_t)r3 * 64 + d];
            float2 p, q;
            p = __half22float2(*(__half2*)&u0.x); q = __half22float2(*(__half2*)&u0.y);
            a0 = fmaf(p.x, w0, a0); a1 = fmaf(p.y, w0, a1); a2 = fmaf(q.x, w0, a2); a3 = fmaf(q.y, w0, a3);
            p = __half22float2(*(__half2*)&u1.x); q = __half22float2(*(__half2*)&u1.y);
            a0 = fmaf(p.x, w1, a0); a1 = fmaf(p.y, w1, a1); a2 = fmaf(q.x, w1, a2); a3 = fmaf(q.y, w1, a3);
            p = __half22float2(*(__half2*)&u2.x); q = __half22float2(*(__half2*)&u2.y);
            a0 = fmaf(p.x, w2, a0); a1 = fmaf(p.y, w2, a1); a2 = fmaf(q.x, w2, a2); a3 = fmaf(q.y, w2, a3);
            p = __half22float2(*(__half2*)&u3.x); q = __half22float2(*(__half2*)&u3.y);
            a0 = fmaf(p.x, w3, a0); a1 = fmaf(p.y, w3, a1); a2 = fmaf(q.x, w3, a2); a3 = fmaf(q.y, w3, a3);
        }
        for (; j < end; j++) {
            int r = __ldg(&g_src[j]);
            float w = g_dinv[r];
            uint2 u0 = H4[(size_t)r * 64 + d];
            float2 p = __half22float2(*(__half2*)&u0.x);
            float2 q = __half22float2(*(__half2*)&u0.y);
            a0 = fmaf(p.x, w, a0); a1 = fmaf(p.y, w, a1); a2 = fmaf(q.x, w, a2); a3 = fmaf(q.y, w, a3);
        }
        float o0 = fmaf(a0, dc, bi.x);
        float o1 = fmaf(a1, dc, bi.y);
        float o2 = fmaf(a2, dc, bi.z);
        float o3 = fmaf(a3, dc, bi.w);
        *(float4*)&out[(size_t)c * D + 4 * d] = make_float4(o0, o1, o2, o3);
        s0 += o0; s1 += o1; s2 += o2; s3 += o3;
        q0 = fmaf(o0, o0, q0); q1 = fmaf(o1, o1, q1);
        q2 = fmaf(o2, o2, q2); q3 = fmaf(o3, o3, q3);
    }
    atomicAdd(&g_bnstat[4 * d + 0], s0);
    atomicAdd(&g_bnstat[4 * d + 1], s1);
    atomicAdd(&g_bnstat[4 * d + 2], s2);
    atomicAdd(&g_bnstat[4 * d + 3], s3);
    atomicAdd(&g_bnstat[D + 4 * d + 0], q0);
    atomicAdd(&g_bnstat[D + 4 * d + 1], q1);
    atomicAdd(&g_bnstat[D + 4 * d + 2], q2);
    atomicAdd(&g_bnstat[D + 4 * d + 3], q3);
}

// ---------------- BN finalize ----------------
__global__ void k_bn_params(const float* __restrict__ gamma, const float* __restrict__ beta) {
    int d = threadIdx.x;
    float inv_n = 1.0f / (float)NN;
    float mean = g_bnstat[d] * inv_n;
    float var = g_bnstat[D + d] * inv_n - mean * mean;
    float a = gamma[d] * rsqrtf(var + BN_EPS);
    g_bn_a[d] = a;
    g_bn_b[d] = beta[d] - mean * a;
}

__global__ void k_bn_apply(float* __restrict__ out) {
    int idx = blockIdx.x * blockDim.x + threadIdx.x;
    if (idx >= NN * (D / 4)) return;
    int dq = (idx & 63) * 4;
    float4 a = *(const float4*)&g_bn_a[dq];
    float4 b = *(const float4*)&g_bn_b[dq];
    float4 v = ((const float4*)out)[idx];
    float4 o;
    o.x = fmaxf(fmaf(v.x, a.x, b.x), 0.f);
    o.y = fmaxf(fmaf(v.y, a.y, b.y), 0.f);
    o.z = fmaxf(fmaf(v.z, a.z, b.z), 0.f);
    o.w = fmaxf(fmaf(v.w, a.w, b.w), 0.f);
    ((float4*)out)[idx] = o;
}

// ---------------- launch ----------------
extern "C" void kernel_launch(void* const* d_in, const int* in_sizes, int n_in,
                              void* d_out, int out_size) {
    const float* x = (const float*)d_in[0];
    const int* ei = (const int*)d_in[1];
    const float* W = (const float*)d_in[2];
    const float* bias = (const float*)d_in[3];
    const float* gamma = (const float*)d_in[4];
    const float* beta = (const float*)d_in[5];
    float* out = (float*)d_out;

    __half* h;  cudaGetSymbolAddress((void**)&h, g_h);
    int* cnt;   cudaGetSymbolAddress((void**)&cnt, g_cnt);
    float* bns; cudaGetSymbolAddress((void**)&bns, g_bnstat);

    cudaMemsetAsync(cnt, 0, NN * sizeof(int));
    cudaMemsetAsync(bns, 0, 2 * D * sizeof(float));

    // 1: gemm (+edge count)   2: scan1   3: fill (+boff)   4: gather (profiled)
    dim3 ggrid((NN + 127) / 128, D / 64);
    k_gemm_bf16<<<ggrid, 256>>>(x, W, h, ei);

    k_scan1<<<NSCB, 256>>>();
    k_fill<<<(NE + 255) / 256, 256>>>(ei);

    k_gather_bn<<<2960, 64>>>(bias, out);

    k_bn_params<<<1, 256>>>(gamma, beta);

    int q = NN * (D / 4);
    k_bn_apply<<<(q + 255) / 256, 256>>>(out);
}